// round 1
// baseline (speedup 1.0000x reference)
#include <cuda_runtime.h>
#include <math.h>

#define BB 2
#define LL 2048
#define DM 1024
#define NH 16
#define HD 64
#define DFF 4096
#define NTOK (BB*LL)
#define LN_EPS 1e-5f

// ---------------- scratch (no allocation allowed) ----------------
__device__ float g_xn [NTOK*DM];
__device__ float g_q  [NTOK*DM];
__device__ float g_k  [NTOK*DM];
__device__ float g_v  [NTOK*DM];
__device__ float g_o  [NTOK*DM];
__device__ float g_x2 [NTOK*DM];
__device__ float g_xn2[NTOK*DM];
__device__ float g_h  [NTOK*DFF];

// ---------------- LayerNorm: one block per row (D=1024) ----------------
__global__ void ln_kernel(const float* __restrict__ x, const float* __restrict__ g,
                          const float* __restrict__ b, float* __restrict__ y)
{
    int row = blockIdx.x;
    int t = threadIdx.x;
    const float4* xr = (const float4*)(x + (size_t)row * DM);
    float4 v = xr[t];
    float s  = v.x + v.y + v.z + v.w;
    float ss = v.x*v.x + v.y*v.y + v.z*v.z + v.w*v.w;
#pragma unroll
    for (int o = 16; o; o >>= 1) {
        s  += __shfl_xor_sync(0xffffffffu, s,  o);
        ss += __shfl_xor_sync(0xffffffffu, ss, o);
    }
    __shared__ float sh_s[8], sh_ss[8];
    int w = t >> 5, lane = t & 31;
    if (lane == 0) { sh_s[w] = s; sh_ss[w] = ss; }
    __syncthreads();
    if (t < 32) {
        s  = (t < 8) ? sh_s[t]  : 0.f;
        ss = (t < 8) ? sh_ss[t] : 0.f;
#pragma unroll
        for (int o = 4; o; o >>= 1) {
            s  += __shfl_xor_sync(0xffffffffu, s,  o);
            ss += __shfl_xor_sync(0xffffffffu, ss, o);
        }
        if (t == 0) { sh_s[0] = s; sh_ss[0] = ss; }
    }
    __syncthreads();
    float mu  = sh_s[0] * (1.f / DM);
    float var = sh_ss[0] * (1.f / DM) - mu * mu;
    float inv = rsqrtf(var + LN_EPS);
    float4 gv = ((const float4*)g)[t];
    float4 bv = ((const float4*)b)[t];
    float4 o4;
    o4.x = (v.x - mu) * inv * gv.x + bv.x;
    o4.y = (v.y - mu) * inv * gv.y + bv.y;
    o4.z = (v.z - mu) * inv * gv.z + bv.z;
    o4.w = (v.w - mu) * inv * gv.w + bv.w;
    ((float4*)(y + (size_t)row * DM))[t] = o4;
}

// ---------------- SGEMM: C[M,N] = A[M,K] @ B[K,N] + bias (+res) (relu) ----------------
// 128x128 tile, BK=16, 256 threads, 8x8 microtile.
template<bool RELU, bool RES>
__global__ __launch_bounds__(256)
void sgemm_kernel(const float* __restrict__ A, const float* __restrict__ Bm,
                  const float* __restrict__ bias, const float* __restrict__ res,
                  float* __restrict__ C, int M, int N, int K)
{
    __shared__ float As[16][128];
    __shared__ float Bs[16][128];
    int t  = threadIdx.x;
    int m0 = blockIdx.y * 128;
    int n0 = blockIdx.x * 128;
    int ty = t >> 4, tx = t & 15;

    float acc[8][8];
#pragma unroll
    for (int i = 0; i < 8; i++)
#pragma unroll
        for (int j = 0; j < 8; j++) acc[i][j] = 0.f;

    int arow = t >> 2;       // 0..63 (and +64)
    int ac4  = t & 3;        // float4 index within 16-wide K slab
    int brow = t >> 5;       // 0..7 (and +8)
    int bc4  = t & 31;       // float4 index within 128-wide N slab

    for (int k0 = 0; k0 < K; k0 += 16) {
        float4 a0 = *(const float4*)(A + (size_t)(m0 + arow)      * K + k0 + ac4 * 4);
        float4 a1 = *(const float4*)(A + (size_t)(m0 + arow + 64) * K + k0 + ac4 * 4);
        float4 b0 = *(const float4*)(Bm + (size_t)(k0 + brow)     * N + n0 + bc4 * 4);
        float4 b1 = *(const float4*)(Bm + (size_t)(k0 + brow + 8) * N + n0 + bc4 * 4);
        __syncthreads();
        As[ac4*4+0][arow] = a0.x; As[ac4*4+1][arow] = a0.y;
        As[ac4*4+2][arow] = a0.z; As[ac4*4+3][arow] = a0.w;
        As[ac4*4+0][arow+64] = a1.x; As[ac4*4+1][arow+64] = a1.y;
        As[ac4*4+2][arow+64] = a1.z; As[ac4*4+3][arow+64] = a1.w;
        *(float4*)(&Bs[brow][bc4*4])     = b0;
        *(float4*)(&Bs[brow+8][bc4*4])   = b1;
        __syncthreads();
#pragma unroll
        for (int kk = 0; kk < 16; kk++) {
            float4 ra0 = *(const float4*)(&As[kk][ty*8]);
            float4 ra1 = *(const float4*)(&As[kk][ty*8+4]);
            float4 rb0 = *(const float4*)(&Bs[kk][tx*8]);
            float4 rb1 = *(const float4*)(&Bs[kk][tx*8+4]);
            float ra[8] = {ra0.x, ra0.y, ra0.z, ra0.w, ra1.x, ra1.y, ra1.z, ra1.w};
            float rb[8] = {rb0.x, rb0.y, rb0.z, rb0.w, rb1.x, rb1.y, rb1.z, rb1.w};
#pragma unroll
            for (int i = 0; i < 8; i++)
#pragma unroll
                for (int j = 0; j < 8; j++)
                    acc[i][j] += ra[i] * rb[j];
        }
    }

    float bj[8];
#pragma unroll
    for (int j = 0; j < 8; j++) bj[j] = bias[n0 + tx*8 + j];

#pragma unroll
    for (int i = 0; i < 8; i++) {
        size_t crow = (size_t)(m0 + ty*8 + i) * N + n0 + tx*8;
        float val[8];
#pragma unroll
        for (int j = 0; j < 8; j++) {
            float vv = acc[i][j] + bj[j];
            if (RES)  vv += res[crow + j];
            if (RELU) vv = fmaxf(vv, 0.f);
            val[j] = vv;
        }
        *(float4*)(C + crow)     = make_float4(val[0], val[1], val[2], val[3]);
        *(float4*)(C + crow + 4) = make_float4(val[4], val[5], val[6], val[7]);
    }
}

// ---------------- RoPE (heads < 8) + q scale (all heads) ----------------
__global__ void rope_kernel(float* __restrict__ q, float* __restrict__ k)
{
    int idx = blockIdx.x * blockDim.x + threadIdx.x;   // pair index
    const int total = NTOK * NH * (HD / 2);
    if (idx >= total) return;
    int i   = idx & 31;            // rotation pair 0..31
    int h   = (idx >> 5) & 15;
    int tok = idx >> 9;            // 0..4095
    int l   = tok & (LL - 1);
    size_t base = (size_t)tok * DM + h * HD + 2 * i;

    float q1 = q[base], q2 = q[base + 1];
    if (h < 8) {
        double invf = pow(10000.0, -(double)i / 32.0);
        float ang = (float)((double)l * invf);   // matches fp32-ish table build
        float cs = (float)cos((double)ang);
        float sn = (float)sin((double)ang);
        float qe = q1 * cs - q2 * sn;
        float qo = q1 * sn + q2 * cs;
        q1 = qe; q2 = qo;
        float k1 = k[base], k2 = k[base + 1];
        k[base]     = k1 * cs - k2 * sn;
        k[base + 1] = k1 * sn + k2 * cs;
    }
    q[base]     = q1 * 0.125f;
    q[base + 1] = q2 * 0.125f;
}

// ---------------- Flash attention (fp32, no mask) ----------------
// grid: (L/64, H, B); 256 threads; thread (r=t/4, quad=t%3..) owns row r,
// S-columns quad*16..+15, output dims quad*16..+15. Q row in registers.
__global__ __launch_bounds__(256, 2)
void attn_kernel(const float* __restrict__ q, const float* __restrict__ k,
                 const float* __restrict__ v, float* __restrict__ o)
{
    extern __shared__ float sm[];
    float* k_s = sm;             // [64][64]
    float* v_s = sm + 64 * 64;   // [64][64]
    float* p_s = sm + 2 * 64 * 64; // [64][64]

    int qt = blockIdx.x;
    int h  = blockIdx.y;
    int b  = blockIdx.z;
    int t  = threadIdx.x;
    int r    = t >> 2;
    int quad = t & 3;

    size_t qbase = ((size_t)b * LL + qt * 64 + r) * DM + h * HD;
    float4 qreg[16];
#pragma unroll
    for (int i = 0; i < 16; i++) qreg[i] = *(const float4*)(q + qbase + i * 4);

    float acc[16];
#pragma unroll
    for (int i = 0; i < 16; i++) acc[i] = 0.f;
    float m = -1e30f, lsum = 0.f;

    const float* kbh = k + (size_t)b * LL * DM + h * HD;
    const float* vbh = v + (size_t)b * LL * DM + h * HD;

    for (int j = 0; j < LL / 64; j++) {
        __syncthreads();   // previous PV finished reading v_s/p_s
#pragma unroll
        for (int u = 0; u < 4; u++) {
            int idx = t + u * 256;
            int rr = idx >> 4, c4 = idx & 15;
            *(float4*)(k_s + rr * 64 + c4 * 4) =
                *(const float4*)(kbh + (size_t)(j * 64 + rr) * DM + c4 * 4);
            *(float4*)(v_s + rr * 64 + c4 * 4) =
                *(const float4*)(vbh + (size_t)(j * 64 + rr) * DM + c4 * 4);
        }
        __syncthreads();

        // S = q . k^T for this thread's 16 columns
        float s[16];
#pragma unroll
        for (int c16 = 0; c16 < 16; c16++) {
            int c = quad * 16 + c16;
            const float* kr = k_s + c * 64;
            float sv = 0.f;
#pragma unroll
            for (int d4 = 0; d4 < 16; d4++) {
                float4 kk = *(const float4*)(kr + d4 * 4);
                sv += qreg[d4].x * kk.x + qreg[d4].y * kk.y
                    + qreg[d4].z * kk.z + qreg[d4].w * kk.w;
            }
            s[c16] = sv;
        }

        // online softmax (row = 4 lanes: quad group)
        float mloc = s[0];
#pragma unroll
        for (int c16 = 1; c16 < 16; c16++) mloc = fmaxf(mloc, s[c16]);
        mloc = fmaxf(mloc, __shfl_xor_sync(0xffffffffu, mloc, 1));
        mloc = fmaxf(mloc, __shfl_xor_sync(0xffffffffu, mloc, 2));
        float mnew  = fmaxf(m, mloc);
        float alpha = __expf(m - mnew);
        float psum = 0.f;
#pragma unroll
        for (int c16 = 0; c16 < 16; c16++) {
            float p = __expf(s[c16] - mnew);
            s[c16] = p;
            psum += p;
        }
        psum += __shfl_xor_sync(0xffffffffu, psum, 1);
        psum += __shfl_xor_sync(0xffffffffu, psum, 2);
        lsum = lsum * alpha + psum;
        m = mnew;
#pragma unroll
        for (int i = 0; i < 16; i++) acc[i] *= alpha;

#pragma unroll
        for (int c16 = 0; c16 < 16; c16++)
            p_s[r * 64 + quad * 16 + c16] = s[c16];
        __syncthreads();

        // acc += P @ V  (this thread: dims quad*16..+15 of row r)
#pragma unroll 4
        for (int c = 0; c < 64; c++) {
            float pv = p_s[r * 64 + c];
            const float* vr = v_s + c * 64 + quad * 16;
            float4 v0 = *(const float4*)(vr);
            float4 v1 = *(const float4*)(vr + 4);
            float4 v2 = *(const float4*)(vr + 8);
            float4 v3 = *(const float4*)(vr + 12);
            acc[0]  += pv * v0.x; acc[1]  += pv * v0.y; acc[2]  += pv * v0.z; acc[3]  += pv * v0.w;
            acc[4]  += pv * v1.x; acc[5]  += pv * v1.y; acc[6]  += pv * v1.z; acc[7]  += pv * v1.w;
            acc[8]  += pv * v2.x; acc[9]  += pv * v2.y; acc[10] += pv * v2.z; acc[11] += pv * v2.w;
            acc[12] += pv * v3.x; acc[13] += pv * v3.y; acc[14] += pv * v3.z; acc[15] += pv * v3.w;
        }
    }

    float invl = 1.f / lsum;
    size_t obase = ((size_t)b * LL + qt * 64 + r) * DM + h * HD + quad * 16;
#pragma unroll
    for (int i4 = 0; i4 < 4; i4++) {
        float4 w = make_float4(acc[i4*4+0] * invl, acc[i4*4+1] * invl,
                               acc[i4*4+2] * invl, acc[i4*4+3] * invl);
        *(float4*)(o + obase + i4 * 4) = w;
    }
}

// ---------------- launcher ----------------
extern "C" void kernel_launch(void* const* d_in, const int* in_sizes, int n_in,
                              void* d_out, int out_size)
{
    const float* x     = (const float*)d_in[0];
    const float* Wq    = (const float*)d_in[1];
    const float* bq    = (const float*)d_in[2];
    const float* Wk    = (const float*)d_in[3];
    const float* bk    = (const float*)d_in[4];
    const float* Wv    = (const float*)d_in[5];
    const float* bv    = (const float*)d_in[6];
    const float* Wo    = (const float*)d_in[7];
    const float* bo    = (const float*)d_in[8];
    const float* ln1_g = (const float*)d_in[9];
    const float* ln1_b = (const float*)d_in[10];
    const float* ln2_g = (const float*)d_in[11];
    const float* ln2_b = (const float*)d_in[12];
    const float* W1    = (const float*)d_in[13];
    const float* b1    = (const float*)d_in[14];
    const float* W2    = (const float*)d_in[15];
    const float* b2    = (const float*)d_in[16];
    float* out = (float*)d_out;

    float *xn, *q, *k, *v, *o, *x2, *xn2, *hb;
    cudaGetSymbolAddress((void**)&xn,  g_xn);
    cudaGetSymbolAddress((void**)&q,   g_q);
    cudaGetSymbolAddress((void**)&k,   g_k);
    cudaGetSymbolAddress((void**)&v,   g_v);
    cudaGetSymbolAddress((void**)&o,   g_o);
    cudaGetSymbolAddress((void**)&x2,  g_x2);
    cudaGetSymbolAddress((void**)&xn2, g_xn2);
    cudaGetSymbolAddress((void**)&hb,  g_h);

    // LN1 (only feeds Q)
    ln_kernel<<<NTOK, 256>>>(x, ln1_g, ln1_b, xn);

    dim3 g1(DM / 128, NTOK / 128);     // (8, 32)
    sgemm_kernel<false, false><<<g1, 256>>>(xn, Wq, bq, nullptr, q, NTOK, DM, DM);
    sgemm_kernel<false, false><<<g1, 256>>>(x,  Wk, bk, nullptr, k, NTOK, DM, DM);
    sgemm_kernel<false, false><<<g1, 256>>>(x,  Wv, bv, nullptr, v, NTOK, DM, DM);

    // RoPE on first 8 heads; q scaled by 1/sqrt(64) everywhere
    const int pairs = NTOK * NH * (HD / 2);
    rope_kernel<<<(pairs + 255) / 256, 256>>>(q, k);

    dim3 ga(LL / 64, NH, BB);          // (32, 16, 2)
    attn_kernel<<<ga, 256, 3 * 64 * 64 * sizeof(float)>>>(q, k, v, o);

    // O projection + residual
    sgemm_kernel<false, true><<<g1, 256>>>(o, Wo, bo, x, x2, NTOK, DM, DM);

    ln_kernel<<<NTOK, 256>>>(x2, ln2_g, ln2_b, xn2);

    dim3 g2(DFF / 128, NTOK / 128);    // (32, 32)
    sgemm_kernel<true, false><<<g2, 256>>>(xn2, W1, b1, nullptr, hb, NTOK, DFF, DM);
    sgemm_kernel<false, true><<<g1, 256>>>(hb, W2, b2, x2, out, NTOK, DM, DFF);
}